// round 9
// baseline (speedup 1.0000x reference)
#include <cuda_runtime.h>
#include <cuda_fp16.h>
#include <cstdint>

#define DINLINE __device__ __forceinline__

// ---------------- problem constants ----------------
#define B_    32
#define F_    128
#define T_    4000
#define H_    256
#define TPAD  4032
#define NCH   80
#define LCH   50
#define EPS_  1e-6f

#define RSTRIDE 264     // halves per smem row (256 + 8 pad)
#define WSM_BYTES (256 * RSTRIDE * 2)      // 135168
#define ASM_BYTES (64 * RSTRIDE * 2)       // 33792
#define SMEM_FC  (WSM_BYTES + ASM_BYTES)   // 168960

// ---------------- device scratch (BSS) ----------------
__device__ float  g_Xt[(size_t)B_ * T_ * F_];      // [B][T][F]
__device__ __half g_W1t[256 * 256];                // [N=256][K=256]
__device__ __half g_W2t[512 * 256];                // [N=512][K=256]
__device__ __half g_H[(size_t)B_ * TPAD * H_];     // [B][TPAD][H] fp16
__device__ float  g_s [(size_t)B_ * T_ * F_];      // [B][T][F]
__device__ float  g_de[(size_t)B_ * T_ * F_];
__device__ __half g_alh[(size_t)B_ * T_ * F_];
__device__ __half g_rh [(size_t)B_ * T_ * F_];
__device__ float  g_chA[NCH * B_ * F_];
__device__ float  g_chB[NCH * B_ * F_];
__device__ float  g_Mst[NCH * B_ * F_];

// ---------------- helpers ----------------
DINLINE uint32_t smem_u32(const void* p) {
    uint32_t a;
    asm("{ .reg .u64 t; cvta.to.shared.u64 t, %1; cvt.u32.u64 %0, t; }" : "=r"(a) : "l"(p));
    return a;
}
DINLINE void ldsm_x4(uint32_t* r, uint32_t addr) {
    asm volatile("ldmatrix.sync.aligned.m8n8.x4.shared.b16 {%0,%1,%2,%3}, [%4];"
                 : "=r"(r[0]), "=r"(r[1]), "=r"(r[2]), "=r"(r[3]) : "r"(addr));
}
DINLINE void ldsm_x2(uint32_t* r, uint32_t addr) {
    asm volatile("ldmatrix.sync.aligned.m8n8.x2.shared.b16 {%0,%1}, [%2];"
                 : "=r"(r[0]), "=r"(r[1]) : "r"(addr));
}
DINLINE void mma16816(float* c, const uint32_t* a, const uint32_t* b) {
    asm volatile("mma.sync.aligned.m16n8k16.row.col.f32.f16.f16.f32 "
                 "{%0,%1,%2,%3}, {%4,%5,%6,%7}, {%8,%9}, {%0,%1,%2,%3};"
                 : "+f"(c[0]), "+f"(c[1]), "+f"(c[2]), "+f"(c[3])
                 : "r"(a[0]), "r"(a[1]), "r"(a[2]), "r"(a[3]), "r"(b[0]), "r"(b[1]));
}
DINLINE void cp16(uint32_t dst, const void* src) {
    asm volatile("cp.async.cg.shared.global [%0], [%1], 16;" :: "r"(dst), "l"(src));
}
DINLINE void cp_commit() { asm volatile("cp.async.commit_group;" ::: "memory"); }
DINLINE void cp_wait0()  { asm volatile("cp.async.wait_group 0;" ::: "memory"); }

DINLINE float sigmoidf_(float x) { return 1.0f / (1.0f + __expf(-x)); }
DINLINE float softplusf_(float x) { return (x > 20.0f) ? x : log1pf(__expf(x)); }

// ---------------- K0: weight transpose + fp16 convert ----------------
__global__ void k_wprep(const float* __restrict__ W1, const float* __restrict__ W2) {
    int idx = blockIdx.x * blockDim.x + threadIdx.x;
    if (idx < 256 * 256) {
        int k = idx >> 8, n = idx & 255;           // W1[k][n]
        g_W1t[n * 256 + k] = __float2half_rn(W1[idx]);
    } else {
        int i2 = idx - 256 * 256;
        if (i2 < 256 * 512) {
            int k = i2 >> 9, n = i2 & 511;         // W2[k][n]
            g_W2t[n * 256 + k] = __float2half_rn(W2[i2]);
        }
    }
}

// ---------------- K1: X [B][F][T] -> Xt [B][T][F] ----------------
__global__ void k_xt(const float* __restrict__ X) {
    __shared__ float tile[32][33];
    int b = blockIdx.z;
    int t0 = blockIdx.x * 32, f0 = blockIdx.y * 32;
    int tx = threadIdx.x, ty = threadIdx.y;
    #pragma unroll
    for (int j = 0; j < 4; j++) {
        int f = f0 + ty + j * 8;
        int t = t0 + tx;
        tile[ty + j * 8][tx] = X[((size_t)b * F_ + f) * T_ + t];
    }
    __syncthreads();
    #pragma unroll
    for (int j = 0; j < 4; j++) {
        int t = t0 + ty + j * 8;
        int f = f0 + tx;
        g_Xt[((size_t)b * T_ + t) * F_ + f] = tile[tx][ty + j * 8];
    }
}

// ---------------- fc core: 64x256 tile vs resident 256x256 weights ----------------
// 8 warps, each owns a 32-wide n slice; acc[4][4][4]

// ---------------- k_fc1: H = relu([Xprev|Xcur] @ W1 + b1) ----------------
__global__ void __launch_bounds__(256, 1) k_fc1(const float* __restrict__ b1) {
    extern __shared__ __align__(16) char sm[];
    __half* Ws = (__half*)sm;                       // [256][RSTRIDE]
    __half* As = (__half*)(sm + WSM_BYTES);         // [64][RSTRIDE]
    uint32_t Ws_b = smem_u32(Ws), As_b = smem_u32(As);

    int b = blockIdx.y;
    int tid = threadIdx.x;
    int lane = tid & 31, warp = tid >> 5;
    int wn = warp * 32;
    int l16 = lane & 15;
    int l4 = lane >> 2, l2 = (lane & 3) * 2;

    // ---- load W1 into smem (once) ----
    #pragma unroll
    for (int p = 0; p < 32; p++) {
        int idx = p * 256 + tid;
        int n = idx >> 5, seg = idx & 31;
        cp16(Ws_b + (n * RSTRIDE + seg * 8) * 2, g_W1t + n * 256 + seg * 8);
    }
    cp_commit();

    for (int it = blockIdx.x; it < (T_ + 63) / 64; it += gridDim.x) {
        int t0 = it * 64;

        // ---- A tile fill: row r -> [Xt[b][t-1][:128] | Xt[b][t][:128]] ----
        {
            int r = tid >> 2, q = tid & 3;
            int t = t0 + r;
            int tc = min(t, T_ - 1);
            int tp = min(max(t - 1, 0), T_ - 1);
            const float* rowp = g_Xt + ((size_t)b * T_ + tp) * F_;
            const float* rowc = g_Xt + ((size_t)b * T_ + tc) * F_;
            #pragma unroll
            for (int p = 0; p < 16; p++) {
                int col = q * 64 + p * 4;
                const float* src = (col < 128) ? (rowp + col) : (rowc + col - 128);
                float4 v = *(const float4*)src;
                __half2* dst = (__half2*)&As[r * RSTRIDE + col];
                dst[0] = __floats2half2_rn(v.x, v.y);
                dst[1] = __floats2half2_rn(v.z, v.w);
            }
        }
        cp_wait0();           // W resident after first pass (no-op later)
        __syncthreads();

        float acc[4][4][4];
        #pragma unroll
        for (int i = 0; i < 4; i++)
            #pragma unroll
            for (int j = 0; j < 4; j++)
                #pragma unroll
                for (int v = 0; v < 4; v++) acc[i][j][v] = 0.0f;

        #pragma unroll
        for (int kc = 0; kc < 16; kc++) {
            int kcol = kc * 16;
            uint32_t a[4][4];
            #pragma unroll
            for (int i = 0; i < 4; i++) {
                int row = i * 16 + l16;
                int col = kcol + (lane >> 4) * 8;
                ldsm_x4(a[i], As_b + (row * RSTRIDE + col) * 2);
            }
            uint32_t bf[4][2];
            #pragma unroll
            for (int j = 0; j < 4; j++) {
                int nrow = wn + j * 8 + (l16 & 7);
                int col = kcol + (l16 >> 3) * 8;
                ldsm_x2(bf[j], Ws_b + (nrow * RSTRIDE + col) * 2);
            }
            #pragma unroll
            for (int i = 0; i < 4; i++)
                #pragma unroll
                for (int j = 0; j < 4; j++)
                    mma16816(acc[i][j], a[i], bf[j]);
        }

        // ---- epi1: relu(+b1) -> g_H fp16 ----
        #pragma unroll
        for (int j = 0; j < 4; j++) {
            int n0 = wn + j * 8 + l2;
            float bb0 = b1[n0], bb1 = b1[n0 + 1];
            #pragma unroll
            for (int i = 0; i < 4; i++) {
                int r0 = i * 16 + l4;
                int r1 = r0 + 8;
                float h00 = fmaxf(acc[i][j][0] + bb0, 0.0f);
                float h01 = fmaxf(acc[i][j][1] + bb1, 0.0f);
                float h10 = fmaxf(acc[i][j][2] + bb0, 0.0f);
                float h11 = fmaxf(acc[i][j][3] + bb1, 0.0f);
                *(__half2*)&g_H[((size_t)b * TPAD + t0 + r0) * H_ + n0] = __floats2half2_rn(h00, h01);
                *(__half2*)&g_H[((size_t)b * TPAD + t0 + r1) * H_ + n0] = __floats2half2_rn(h10, h11);
            }
        }
        __syncthreads();      // protect As before next fill
    }
}

// ---------------- k_fc2: params = act(H @ W2half + b2half) ----------------
__global__ void __launch_bounds__(256, 1) k_fc2(const float* __restrict__ b2) {
    extern __shared__ __align__(16) char sm[];
    __half* Ws = (__half*)sm;
    __half* As = (__half*)(sm + WSM_BYTES);
    uint32_t Ws_b = smem_u32(Ws), As_b = smem_u32(As);

    int b = blockIdx.y;
    int half = blockIdx.z;
    int tid = threadIdx.x;
    int lane = tid & 31, warp = tid >> 5;
    int wn = warp * 32;
    int l16 = lane & 15;
    int l4 = lane >> 2, l2 = (lane & 3) * 2;

    const __half* W2base = g_W2t + (size_t)half * 256 * 256;

    // ---- load W2 half into smem (once) ----
    #pragma unroll
    for (int p = 0; p < 32; p++) {
        int idx = p * 256 + tid;
        int n = idx >> 5, seg = idx & 31;
        cp16(Ws_b + (n * RSTRIDE + seg * 8) * 2, W2base + n * 256 + seg * 8);
    }
    cp_commit();

    for (int it = blockIdx.x; it < (T_ + 63) / 64; it += gridDim.x) {
        int t0 = it * 64;

        // ---- H tile fill via cp.async (fp16 already) ----
        #pragma unroll
        for (int p = 0; p < 8; p++) {
            int idx = p * 256 + tid;
            int r = idx >> 5, seg = idx & 31;
            cp16(As_b + (r * RSTRIDE + seg * 8) * 2,
                 g_H + ((size_t)b * TPAD + t0 + r) * H_ + seg * 8);
        }
        cp_commit();
        cp_wait0();
        __syncthreads();

        float acc[4][4][4];
        #pragma unroll
        for (int i = 0; i < 4; i++)
            #pragma unroll
            for (int j = 0; j < 4; j++)
                #pragma unroll
                for (int v = 0; v < 4; v++) acc[i][j][v] = 0.0f;

        #pragma unroll
        for (int kc = 0; kc < 16; kc++) {
            int kcol = kc * 16;
            uint32_t a[4][4];
            #pragma unroll
            for (int i = 0; i < 4; i++) {
                int row = i * 16 + l16;
                int col = kcol + (lane >> 4) * 8;
                ldsm_x4(a[i], As_b + (row * RSTRIDE + col) * 2);
            }
            uint32_t bf[4][2];
            #pragma unroll
            for (int j = 0; j < 4; j++) {
                int nrow = wn + j * 8 + (l16 & 7);
                int col = kcol + (l16 >> 3) * 8;
                ldsm_x2(bf[j], Ws_b + (nrow * RSTRIDE + col) * 2);
            }
            #pragma unroll
            for (int i = 0; i < 4; i++)
                #pragma unroll
                for (int j = 0; j < 4; j++)
                    mma16816(acc[i][j], a[i], bf[j]);
        }

        // ---- epi2: activation split + stores (s,de fp32; al,r fp16) ----
        #pragma unroll
        for (int j = 0; j < 4; j++) {
            int ng = half * 256 + wn + j * 8 + l2;
            int q = ng >> 7;                      // 0:s 1:alpha 2:delta 3:r
            int f = ng & 127;
            float bb0 = b2[ng], bb1 = b2[ng + 1];
            #pragma unroll
            for (int i = 0; i < 4; i++) {
                int r0 = t0 + i * 16 + l4;
                int r1 = r0 + 8;
                float v00 = acc[i][j][0] + bb0, v01 = acc[i][j][1] + bb1;
                float v10 = acc[i][j][2] + bb0, v11 = acc[i][j][3] + bb1;
                if (q == 2) {
                    v00 = softplusf_(v00); v01 = softplusf_(v01);
                    v10 = softplusf_(v10); v11 = softplusf_(v11);
                } else {
                    v00 = sigmoidf_(v00); v01 = sigmoidf_(v01);
                    v10 = sigmoidf_(v10); v11 = sigmoidf_(v11);
                }
                size_t o0 = ((size_t)b * T_ + r0) * F_ + f;
                size_t o1 = ((size_t)b * T_ + r1) * F_ + f;
                if (q == 0) {
                    if (r0 < T_) *(float2*)&g_s[o0] = make_float2(v00, v01);
                    if (r1 < T_) *(float2*)&g_s[o1] = make_float2(v10, v11);
                } else if (q == 2) {
                    if (r0 < T_) *(float2*)&g_de[o0] = make_float2(v00, v01);
                    if (r1 < T_) *(float2*)&g_de[o1] = make_float2(v10, v11);
                } else if (q == 1) {
                    if (r0 < T_) *(__half2*)&g_alh[o0] = __floats2half2_rn(v00, v01);
                    if (r1 < T_) *(__half2*)&g_alh[o1] = __floats2half2_rn(v10, v11);
                } else {
                    if (r0 < T_) *(__half2*)&g_rh[o0] = __floats2half2_rn(v00, v01);
                    if (r1 < T_) *(__half2*)&g_rh[o1] = __floats2half2_rn(v10, v11);
                }
            }
        }
        __syncthreads();      // protect As before next fill
    }
}

// ---------------- K3a: per-chunk recurrence composition ----------------
__global__ void k_scan_a() {
    int ch = blockIdx.x, b = blockIdx.y, f = threadIdx.x;
    int t0 = ch * LCH;
    float Aa = 1.0f, Bb = 0.0f;
    const float* sp = g_s  + ((size_t)b * T_ + t0) * F_ + f;
    const float* xp = g_Xt + ((size_t)b * T_ + t0) * F_ + f;
    for (int tl = 0; tl < LCH; tl++) {
        float s = sp[tl * F_];
        float x = xp[tl * F_];
        float a = 1.0f - s;
        Bb = fmaf(a, Bb, s * x);
        Aa *= a;
    }
    g_chA[(ch * B_ + b) * F_ + f] = Aa;
    g_chB[(ch * B_ + b) * F_ + f] = Bb;
}

// ---------------- K3b: scan across chunks ----------------
__global__ void k_scan_b() {
    int b = blockIdx.x, f = threadIdx.x;
    float M = 0.0f;
    for (int ch = 0; ch < NCH; ch++) {
        int idx = (ch * B_ + b) * F_ + f;
        g_Mst[idx] = M;
        M = fmaf(g_chA[idx], M, g_chB[idx]);
    }
}

// ---------------- K3c: replay + PCEN + coalesced [B][F][T] output ----------------
__global__ void k_scan_c(float* __restrict__ out) {
    __shared__ float tile[128][51];
    int ch = blockIdx.x, b = blockIdx.y, f = threadIdx.x;
    int t0 = ch * LCH;
    float M = g_Mst[(ch * B_ + b) * F_ + f];
    const size_t base = ((size_t)b * T_ + t0) * F_ + f;

    for (int tl = 0; tl < LCH; tl++) {
        size_t o = base + (size_t)tl * F_;
        float s  = g_s[o];
        float x  = g_Xt[o];
        float al = __half2float(g_alh[o]);
        float de = g_de[o];
        float r  = __half2float(g_rh[o]);
        M = fmaf(s, x - M, M);
        float pM = __powf(M + EPS_, al);
        float u  = x / pM + de;
        float norm = __powf(u, r) - __powf(de, r);
        tile[f][tl] = norm;
    }
    __syncthreads();
    for (int p = 0; p < LCH; p++) {
        int i = threadIdx.x + p * 128;
        int rr = i / LCH, cc = i % LCH;
        out[((size_t)b * F_ + rr) * T_ + t0 + cc] = tile[rr][cc];
    }
}

// ---------------- launch ----------------
extern "C" void kernel_launch(void* const* d_in, const int* in_sizes, int n_in,
                              void* d_out, int out_size) {
    const float* X  = (const float*)d_in[0];
    const float* W1 = (const float*)d_in[1];
    const float* b1 = (const float*)d_in[2];
    const float* W2 = (const float*)d_in[3];
    const float* b2 = (const float*)d_in[4];
    float* out = (float*)d_out;

    cudaFuncSetAttribute(k_fc1, cudaFuncAttributeMaxDynamicSharedMemorySize, SMEM_FC);
    cudaFuncSetAttribute(k_fc2, cudaFuncAttributeMaxDynamicSharedMemorySize, SMEM_FC);

    int wtot = 256 * 256 + 256 * 512;
    k_wprep<<<(wtot + 255) / 256, 256>>>(W1, W2);
    k_xt<<<dim3(T_ / 32, F_ / 32, B_), dim3(32, 8)>>>(X);
    k_fc1<<<dim3(4, B_), 256, SMEM_FC>>>(b1);
    k_fc2<<<dim3(2, B_, 2), 256, SMEM_FC>>>(b2);
    k_scan_a<<<dim3(NCH, B_), 128>>>();
    k_scan_b<<<B_, 128>>>();
    k_scan_c<<<dim3(NCH, B_), 128>>>(out);
}

// round 11
// speedup vs baseline: 1.2446x; 1.2446x over previous
#include <cuda_runtime.h>
#include <cuda_fp16.h>
#include <cstdint>

#define DINLINE __device__ __forceinline__

// ---------------- problem constants ----------------
#define B_    32
#define F_    128
#define T_    4000
#define H_    256
#define TPAD  4032
#define NCH   80
#define LCH   50
#define EPS_  1e-6f

#define RSTRIDE 264     // halves per A-tile smem row (256 + 8 pad)
#define WSTRIDE 72      // halves per W-chunk smem row (64 + 8 pad)
#define ABYTES  (64 * RSTRIDE * 2)         // 33792
#define WBYTES  (128 * WSTRIDE * 2)        // 18432
#define SMEM_FC (ABYTES + 2 * WBYTES)      // 70656

// ---------------- device scratch (BSS) ----------------
__device__ float  g_Xt[(size_t)B_ * T_ * F_];      // [B][T][F] fp32 (scan)
__device__ __half g_Xh[(size_t)B_ * T_ * F_];      // [B][T][F] fp16 (gemm A)
__device__ __half g_W1t[256 * 256];                // [N=256][K=256]
__device__ __half g_W2t[512 * 256];                // [N=512][K=256]
__device__ __half g_H[(size_t)B_ * TPAD * H_];     // [B][TPAD][H] fp16
__device__ float  g_s [(size_t)B_ * T_ * F_];      // [B][T][F]
__device__ float  g_de[(size_t)B_ * T_ * F_];
__device__ __half g_alh[(size_t)B_ * T_ * F_];
__device__ __half g_rh [(size_t)B_ * T_ * F_];
__device__ float  g_chA[NCH * B_ * F_];
__device__ float  g_chB[NCH * B_ * F_];
__device__ float  g_Mst[NCH * B_ * F_];

// ---------------- helpers ----------------
DINLINE uint32_t smem_u32(const void* p) {
    uint32_t a;
    asm("{ .reg .u64 t; cvta.to.shared.u64 t, %1; cvt.u32.u64 %0, t; }" : "=r"(a) : "l"(p));
    return a;
}
DINLINE void ldsm_x4(uint32_t* r, uint32_t addr) {
    asm volatile("ldmatrix.sync.aligned.m8n8.x4.shared.b16 {%0,%1,%2,%3}, [%4];"
                 : "=r"(r[0]), "=r"(r[1]), "=r"(r[2]), "=r"(r[3]) : "r"(addr));
}
DINLINE void ldsm_x2(uint32_t* r, uint32_t addr) {
    asm volatile("ldmatrix.sync.aligned.m8n8.x2.shared.b16 {%0,%1}, [%2];"
                 : "=r"(r[0]), "=r"(r[1]) : "r"(addr));
}
DINLINE void mma16816(float* c, const uint32_t* a, const uint32_t* b) {
    asm volatile("mma.sync.aligned.m16n8k16.row.col.f32.f16.f16.f32 "
                 "{%0,%1,%2,%3}, {%4,%5,%6,%7}, {%8,%9}, {%0,%1,%2,%3};"
                 : "+f"(c[0]), "+f"(c[1]), "+f"(c[2]), "+f"(c[3])
                 : "r"(a[0]), "r"(a[1]), "r"(a[2]), "r"(a[3]), "r"(b[0]), "r"(b[1]));
}
DINLINE void cp16(uint32_t dst, const void* src) {
    asm volatile("cp.async.cg.shared.global [%0], [%1], 16;" :: "r"(dst), "l"(src));
}
DINLINE void cp_commit() { asm volatile("cp.async.commit_group;" ::: "memory"); }
DINLINE void cp_wait0()  { asm volatile("cp.async.wait_group 0;" ::: "memory"); }

DINLINE float sigmoidf_(float x) { return 1.0f / (1.0f + __expf(-x)); }
DINLINE float softplusf_(float x) { return (x > 20.0f) ? x : log1pf(__expf(x)); }

// ---------------- K0: weight transpose + fp16 convert ----------------
__global__ void k_wprep(const float* __restrict__ W1, const float* __restrict__ W2) {
    int idx = blockIdx.x * blockDim.x + threadIdx.x;
    if (idx < 256 * 256) {
        int k = idx >> 8, n = idx & 255;           // W1[k][n]
        g_W1t[n * 256 + k] = __float2half_rn(W1[idx]);
    } else {
        int i2 = idx - 256 * 256;
        if (i2 < 256 * 512) {
            int k = i2 >> 9, n = i2 & 511;         // W2[k][n]
            g_W2t[n * 256 + k] = __float2half_rn(W2[i2]);
        }
    }
}

// ---------------- K1: X [B][F][T] -> Xt fp32 + Xh fp16 [B][T][F] ----------------
__global__ void k_xt(const float* __restrict__ X) {
    __shared__ float tile[32][33];
    int b = blockIdx.z;
    int t0 = blockIdx.x * 32, f0 = blockIdx.y * 32;
    int tx = threadIdx.x, ty = threadIdx.y;
    #pragma unroll
    for (int j = 0; j < 4; j++) {
        int f = f0 + ty + j * 8;
        int t = t0 + tx;
        tile[ty + j * 8][tx] = X[((size_t)b * F_ + f) * T_ + t];
    }
    __syncthreads();
    #pragma unroll
    for (int j = 0; j < 4; j++) {
        int t = t0 + ty + j * 8;
        int f = f0 + tx;
        float v = tile[tx][ty + j * 8];
        size_t o = ((size_t)b * T_ + t) * F_ + f;
        g_Xt[o] = v;
        g_Xh[o] = __float2half_rn(v);
    }
}

// ================= GEMM core: CTA tile 64(m) x 128(n), 8 warps (2m x 4n) ==========
// warp tile 32x32: acc[2][4][4] = 32 regs

// ---------------- k_fc1: H[:, z*128:(z+1)*128] = relu([Xprev|Xcur] @ W1 + b1) ------
__global__ void __launch_bounds__(256, 3) k_fc1(const float* __restrict__ b1) {
    extern __shared__ __align__(16) char sm[];
    uint32_t As_b = smem_u32(sm);
    uint32_t Ws_b = As_b + ABYTES;

    int t0 = blockIdx.x * 64;
    int b  = blockIdx.y;
    int z  = blockIdx.z;                  // n-half of H
    int tid = threadIdx.x;
    int lane = tid & 31, warp = tid >> 5;
    int wm = (warp >> 2) * 32;
    int wn = (warp & 3) * 32;
    int l16 = lane & 15;
    int l4 = lane >> 2, l2 = (lane & 3) * 2;

    // ---- A tile fill via cp.async from g_Xh: [Xprev(128) | Xcur(128)] ----
    {
        int r = tid >> 2, q = tid & 3;     // 4 threads per row, each 64 halves
        int t = t0 + r;
        int tc = min(t, T_ - 1);
        int tp = min(max(t - 1, 0), T_ - 1);
        #pragma unroll
        for (int s = 0; s < 8; s++) {
            int col = q * 64 + s * 8;
            const __half* src = (col < 128)
                ? (g_Xh + ((size_t)b * T_ + tp) * F_ + col)
                : (g_Xh + ((size_t)b * T_ + tc) * F_ + (col - 128));
            cp16(As_b + (r * RSTRIDE + col) * 2, src);
        }
    }

    // W chunk fill: chunk c covers k in [c*64, c*64+64) for n in [z*128, +128)
    // 128 rows x 8 segs = 1024 cp16 ops = 4 passes of 256 threads
    auto fill = [&](int c, int sel) {
        const __half* base = g_W1t + (size_t)(z * 128) * 256 + c * 64;
        uint32_t wb = Ws_b + sel * WBYTES;
        #pragma unroll
        for (int p = 0; p < 4; p++) {
            int idx = tid + p * 256;
            int n = idx >> 3, seg = idx & 7;
            cp16(wb + (n * WSTRIDE + seg * 8) * 2, base + n * 256 + seg * 8);
        }
        cp_commit();
    };

    float acc[2][4][4];
    #pragma unroll
    for (int i = 0; i < 2; i++)
        #pragma unroll
        for (int j = 0; j < 4; j++)
            #pragma unroll
            for (int v = 0; v < 4; v++) acc[i][j][v] = 0.0f;

    auto mma_chunk = [&](int sel, int cbase) {
        uint32_t wb = Ws_b + sel * WBYTES;
        #pragma unroll
        for (int kk = 0; kk < 4; kk++) {
            int ka = cbase + kk * 16, kw = kk * 16;
            uint32_t a[2][4];
            #pragma unroll
            for (int i = 0; i < 2; i++)
                ldsm_x4(a[i], As_b + ((wm + i * 16 + l16) * RSTRIDE + ka + (lane >> 4) * 8) * 2);
            uint32_t bf[4][2];
            #pragma unroll
            for (int j = 0; j < 4; j++)
                ldsm_x2(bf[j], wb + ((wn + j * 8 + (l16 & 7)) * WSTRIDE + kw + (l16 >> 3) * 8) * 2);
            #pragma unroll
            for (int i = 0; i < 2; i++)
                #pragma unroll
                for (int j = 0; j < 4; j++)
                    mma16816(acc[i][j], a[i], bf[j]);
        }
    };

    fill(0, 0);
    #pragma unroll 1
    for (int c = 0; c < 4; c++) {
        cp_wait0();
        __syncthreads();
        if (c + 1 < 4) fill(c + 1, (c + 1) & 1);
        mma_chunk(c & 1, c * 64);
    }

    // ---- epi1: relu(+b1) -> g_H fp16 ----
    #pragma unroll
    for (int j = 0; j < 4; j++) {
        int n0 = z * 128 + wn + j * 8 + l2;
        float bb0 = b1[n0], bb1 = b1[n0 + 1];
        #pragma unroll
        for (int i = 0; i < 2; i++) {
            int r0 = wm + i * 16 + l4;
            int r1 = r0 + 8;
            float h00 = fmaxf(acc[i][j][0] + bb0, 0.0f);
            float h01 = fmaxf(acc[i][j][1] + bb1, 0.0f);
            float h10 = fmaxf(acc[i][j][2] + bb0, 0.0f);
            float h11 = fmaxf(acc[i][j][3] + bb1, 0.0f);
            *(__half2*)&g_H[((size_t)b * TPAD + t0 + r0) * H_ + n0] = __floats2half2_rn(h00, h01);
            *(__half2*)&g_H[((size_t)b * TPAD + t0 + r1) * H_ + n0] = __floats2half2_rn(h10, h11);
        }
    }
}

// ---------------- k_fc2: param_z = act(H @ W2[:, z*128:+128] + b2) ----------------
__global__ void __launch_bounds__(256, 3) k_fc2(const float* __restrict__ b2) {
    extern __shared__ __align__(16) char sm[];
    uint32_t As_b = smem_u32(sm);
    uint32_t Ws_b = As_b + ABYTES;

    int t0 = blockIdx.x * 64;
    int b  = blockIdx.y;
    int z  = blockIdx.z;                  // n-quarter == param id (0:s 1:al 2:de 3:r)
    int tid = threadIdx.x;
    int lane = tid & 31, warp = tid >> 5;
    int wm = (warp >> 2) * 32;
    int wn = (warp & 3) * 32;
    int l16 = lane & 15;
    int l4 = lane >> 2, l2 = (lane & 3) * 2;

    // ---- A tile fill: H 64x256 fp16 via cp.async ----
    {
        int r = tid >> 2, q = tid & 3;
        const __half* src = g_H + ((size_t)b * TPAD + t0 + r) * H_ + q * 64;
        #pragma unroll
        for (int s = 0; s < 8; s++)
            cp16(As_b + (r * RSTRIDE + q * 64 + s * 8) * 2, src + s * 8);
    }

    auto fill = [&](int c, int sel) {
        const __half* base = g_W2t + (size_t)(z * 128) * 256 + c * 64;
        uint32_t wb = Ws_b + sel * WBYTES;
        #pragma unroll
        for (int p = 0; p < 4; p++) {
            int idx = tid + p * 256;
            int n = idx >> 3, seg = idx & 7;
            cp16(wb + (n * WSTRIDE + seg * 8) * 2, base + n * 256 + seg * 8);
        }
        cp_commit();
    };

    float acc[2][4][4];
    #pragma unroll
    for (int i = 0; i < 2; i++)
        #pragma unroll
        for (int j = 0; j < 4; j++)
            #pragma unroll
            for (int v = 0; v < 4; v++) acc[i][j][v] = 0.0f;

    auto mma_chunk = [&](int sel, int cbase) {
        uint32_t wb = Ws_b + sel * WBYTES;
        #pragma unroll
        for (int kk = 0; kk < 4; kk++) {
            int ka = cbase + kk * 16, kw = kk * 16;
            uint32_t a[2][4];
            #pragma unroll
            for (int i = 0; i < 2; i++)
                ldsm_x4(a[i], As_b + ((wm + i * 16 + l16) * RSTRIDE + ka + (lane >> 4) * 8) * 2);
            uint32_t bf[4][2];
            #pragma unroll
            for (int j = 0; j < 4; j++)
                ldsm_x2(bf[j], wb + ((wn + j * 8 + (l16 & 7)) * WSTRIDE + kw + (l16 >> 3) * 8) * 2);
            #pragma unroll
            for (int i = 0; i < 2; i++)
                #pragma unroll
                for (int j = 0; j < 4; j++)
                    mma16816(acc[i][j], a[i], bf[j]);
        }
    };

    fill(0, 0);
    #pragma unroll 1
    for (int c = 0; c < 4; c++) {
        cp_wait0();
        __syncthreads();
        if (c + 1 < 4) fill(c + 1, (c + 1) & 1);
        mma_chunk(c & 1, c * 64);
    }

    // ---- epi2: one param type per CTA ----
    #pragma unroll
    for (int j = 0; j < 4; j++) {
        int ng = z * 128 + wn + j * 8 + l2;
        int f = ng & 127;
        float bb0 = b2[ng], bb1 = b2[ng + 1];
        #pragma unroll
        for (int i = 0; i < 2; i++) {
            int r0 = t0 + wm + i * 16 + l4;
            int r1 = r0 + 8;
            float v00 = acc[i][j][0] + bb0, v01 = acc[i][j][1] + bb1;
            float v10 = acc[i][j][2] + bb0, v11 = acc[i][j][3] + bb1;
            if (z == 2) {
                v00 = softplusf_(v00); v01 = softplusf_(v01);
                v10 = softplusf_(v10); v11 = softplusf_(v11);
            } else {
                v00 = sigmoidf_(v00); v01 = sigmoidf_(v01);
                v10 = sigmoidf_(v10); v11 = sigmoidf_(v11);
            }
            size_t o0 = ((size_t)b * T_ + r0) * F_ + f;
            size_t o1 = ((size_t)b * T_ + r1) * F_ + f;
            if (z == 0) {
                if (r0 < T_) *(float2*)&g_s[o0] = make_float2(v00, v01);
                if (r1 < T_) *(float2*)&g_s[o1] = make_float2(v10, v11);
            } else if (z == 2) {
                if (r0 < T_) *(float2*)&g_de[o0] = make_float2(v00, v01);
                if (r1 < T_) *(float2*)&g_de[o1] = make_float2(v10, v11);
            } else if (z == 1) {
                if (r0 < T_) *(__half2*)&g_alh[o0] = __floats2half2_rn(v00, v01);
                if (r1 < T_) *(__half2*)&g_alh[o1] = __floats2half2_rn(v10, v11);
            } else {
                if (r0 < T_) *(__half2*)&g_rh[o0] = __floats2half2_rn(v00, v01);
                if (r1 < T_) *(__half2*)&g_rh[o1] = __floats2half2_rn(v10, v11);
            }
        }
    }
}

// ---------------- K3a: per-chunk recurrence composition ----------------
__global__ void k_scan_a() {
    int ch = blockIdx.x, b = blockIdx.y, f = threadIdx.x;
    int t0 = ch * LCH;
    float Aa = 1.0f, Bb = 0.0f;
    const float* sp = g_s  + ((size_t)b * T_ + t0) * F_ + f;
    const float* xp = g_Xt + ((size_t)b * T_ + t0) * F_ + f;
    for (int tl = 0; tl < LCH; tl++) {
        float s = sp[tl * F_];
        float x = xp[tl * F_];
        float a = 1.0f - s;
        Bb = fmaf(a, Bb, s * x);
        Aa *= a;
    }
    g_chA[(ch * B_ + b) * F_ + f] = Aa;
    g_chB[(ch * B_ + b) * F_ + f] = Bb;
}

// ---------------- K3b: scan across chunks ----------------
__global__ void k_scan_b() {
    int b = blockIdx.x, f = threadIdx.x;
    float M = 0.0f;
    for (int ch = 0; ch < NCH; ch++) {
        int idx = (ch * B_ + b) * F_ + f;
        g_Mst[idx] = M;
        M = fmaf(g_chA[idx], M, g_chB[idx]);
    }
}

// ---------------- K3c: replay + PCEN + coalesced [B][F][T] output ----------------
__global__ void k_scan_c(float* __restrict__ out) {
    __shared__ float tile[128][51];
    int ch = blockIdx.x, b = blockIdx.y, f = threadIdx.x;
    int t0 = ch * LCH;
    float M = g_Mst[(ch * B_ + b) * F_ + f];
    const size_t base = ((size_t)b * T_ + t0) * F_ + f;

    for (int tl = 0; tl < LCH; tl++) {
        size_t o = base + (size_t)tl * F_;
        float s  = g_s[o];
        float x  = g_Xt[o];
        float al = __half2float(g_alh[o]);
        float de = g_de[o];
        float r  = __half2float(g_rh[o]);
        M = fmaf(s, x - M, M);
        float pM = __powf(M + EPS_, al);
        float u  = x / pM + de;
        float norm = __powf(u, r) - __powf(de, r);
        tile[f][tl] = norm;
    }
    __syncthreads();
    for (int p = 0; p < LCH; p++) {
        int i = threadIdx.x + p * 128;
        int rr = i / LCH, cc = i % LCH;
        out[((size_t)b * F_ + rr) * T_ + t0 + cc] = tile[rr][cc];
    }
}

// ---------------- launch ----------------
extern "C" void kernel_launch(void* const* d_in, const int* in_sizes, int n_in,
                              void* d_out, int out_size) {
    const float* X  = (const float*)d_in[0];
    const float* W1 = (const float*)d_in[1];
    const float* b1 = (const float*)d_in[2];
    const float* W2 = (const float*)d_in[3];
    const float* b2 = (const float*)d_in[4];
    float* out = (float*)d_out;

    cudaFuncSetAttribute(k_fc1, cudaFuncAttributeMaxDynamicSharedMemorySize, SMEM_FC);
    cudaFuncSetAttribute(k_fc2, cudaFuncAttributeMaxDynamicSharedMemorySize, SMEM_FC);

    int wtot = 256 * 256 + 256 * 512;
    k_wprep<<<(wtot + 255) / 256, 256>>>(W1, W2);
    k_xt<<<dim3(T_ / 32, F_ / 32, B_), dim3(32, 8)>>>(X);
    k_fc1<<<dim3(63, B_, 2), 256, SMEM_FC>>>(b1);
    k_fc2<<<dim3(63, B_, 4), 256, SMEM_FC>>>(b2);
    k_scan_a<<<dim3(NCH, B_), 128>>>();
    k_scan_b<<<B_, 128>>>();
    k_scan_c<<<dim3(NCH, B_), 128>>>(out);
}